// round 14
// baseline (speedup 1.0000x reference)
#include <cuda_runtime.h>
#include <cuda_fp16.h>

// ---------------- problem constants ----------------
#define Bb   2
#define Ss   2048
#define Dd   1024
#define Hh   16
#define HD   64
#define NB   16
#define ROWS 4096        // B*S
#define NQKV 3072        // 3*D

// ---------------- device scratch (fp16) ----------------
__device__ __half g_x     [ROWS * Dd];     // x, [4096][1024] K-contig
__device__ __half g_wqkvT [NQKV * Dd];     // w_qkv^T, [3072][1024] K-contig (n-major)
__device__ __half g_wprojT[Dd * Dd];       // w_proj^T, [1024][1024] K-contig
__device__ __half g_qkv   [ROWS * NQKV];   // QKV out (Q pre-scaled by 0.125)
__device__ __half g_att   [ROWS * Dd];     // attention out
__device__ int    g_mask  [NB * NB];

// ---------------- helpers ----------------
__device__ __forceinline__ unsigned int pack2(float a, float b) {
    __half2 h = __floats2half2_rn(a, b);       // low = a (even col), high = b
    return *(unsigned int*)&h;
}
__device__ __forceinline__ unsigned int ex2h2(unsigned int h2) {
    unsigned int r;
    asm("ex2.approx.f16x2 %0, %1;" : "=r"(r) : "r"(h2));   // 2^x both halves, one MUFU op
    return r;
}
// NON-volatile: pure register compute, dataflow fully captured by constraints.
// Lets ptxas software-pipeline MMAs against fragment loads (MLP was 1 with volatile).
__device__ __forceinline__ void mma16(float* c, const unsigned int* a, const unsigned int* b) {
    asm("mma.sync.aligned.m16n8k16.row.col.f32.f16.f16.f32 "
        "{%0,%1,%2,%3}, {%4,%5,%6,%7}, {%8,%9}, {%0,%1,%2,%3};"
        : "+f"(c[0]), "+f"(c[1]), "+f"(c[2]), "+f"(c[3])
        : "r"(a[0]), "r"(a[1]), "r"(a[2]), "r"(a[3]), "r"(b[0]), "r"(b[1]));
}
__device__ __forceinline__ unsigned int s2u(const void* p) {
    return (unsigned int)__cvta_generic_to_shared(p);
}
__device__ __forceinline__ void cpa16(unsigned int s, const void* g) {
    asm volatile("cp.async.cg.shared.global [%0], [%1], 16;" :: "r"(s), "l"(g));
}
#define CP_COMMIT() asm volatile("cp.async.commit_group;")
template<int N> __device__ __forceinline__ void cp_wait() {
    asm volatile("cp.async.wait_group %0;" :: "n"(N));
}
__device__ __forceinline__ void ldmx4t(unsigned int& r0, unsigned int& r1,
                                       unsigned int& r2, unsigned int& r3, unsigned int addr) {
    asm volatile("ldmatrix.sync.aligned.m8n8.x4.trans.shared.b16 {%0,%1,%2,%3}, [%4];"
                 : "=r"(r0), "=r"(r1), "=r"(r2), "=r"(r3) : "r"(addr));
}

// ---------------- fused prepass: x->fp16, mask canon, both weight transposes ----------------
#define CONV_BLKS 1184
#define TRQ_BX (NQKV / 32)                 // 96
#define TR_BX  (NQKV / 32 + Dd / 32)       // 128
#define TR_BY  (Dd / 32)                   // 32

__global__ void prepass(const float* __restrict__ x, const unsigned char* __restrict__ raw,
                        const float* __restrict__ wq, const float* __restrict__ wp)
{
    __shared__ float tl[32][33];
    const int bid = blockIdx.x;
    const int tid = threadIdx.x;

    if (bid < CONV_BLKS) {
        if (bid == 0 && tid == 0) {
            const unsigned int* w = (const unsigned int*)raw;
            bool all01 = true, allf = true;
            for (int i = 0; i < 64; i++) {
                unsigned int v = w[i];
                if (v != 0u && v != 1u) all01 = false;
                if (v != 0u && v != 0x3F800000u) allf = false;
            }
            if (all01)      for (int i = 0; i < 256; i++) g_mask[i] = (int)w[i];
            else if (allf)  for (int i = 0; i < 256; i++) g_mask[i] = (w[i] != 0u) ? 1 : 0;
            else            for (int i = 0; i < 256; i++) g_mask[i] = raw[i] ? 1 : 0;
        }
        int n4 = ROWS * Dd / 4;
        for (int i = bid * 256 + tid; i < n4; i += CONV_BLKS * 256) {
            float4 v = ((const float4*)x)[i];
            uint2 o;
            o.x = pack2(v.x, v.y);
            o.y = pack2(v.z, v.w);
            ((uint2*)g_x)[i] = o;
        }
    } else {
        int tb = bid - CONV_BLKS;
        int bx = tb % TR_BX;
        int by = tb / TR_BX;
        const float* src; __half* dst; int Nn; int n0;
        if (bx < TRQ_BX) { src = wq; dst = g_wqkvT;  Nn = NQKV; n0 = bx * 32; }
        else             { src = wp; dst = g_wprojT; Nn = Dd;   n0 = (bx - TRQ_BX) * 32; }
        int k0 = by * 32;
        int tx = tid & 31, ty = tid >> 5;  // 32 x 8
        #pragma unroll
        for (int i = 0; i < 32; i += 8)
            tl[ty + i][tx] = src[(size_t)(k0 + ty + i) * Nn + n0 + tx];
        __syncthreads();
        #pragma unroll
        for (int i = 0; i < 32; i += 8)
            dst[(size_t)(n0 + ty + i) * Dd + k0 + tx] = __float2half_rn(tl[tx][ty + i]);
    }
}

// ---------------- fp16 GEMM (R9 config: 128x128x64, occ 2) ----------------
#define GBM 128
#define GBN 128
#define GBK 64
#define RSTR 36
#define TILE_W (128 * RSTR)          // 4608 words
#define STAGE_W (2 * TILE_W)         // 9216 words = 36 KB
#define NSTAGE 3
#define GEMM_SMEM (NSTAGE * STAGE_W * 4)   // 110592 B -> 2 CTAs/SM

__global__ __launch_bounds__(256, 2)
void gemm_f16(const __half* __restrict__ A, const __half* __restrict__ BT,
              const float* __restrict__ bias, void* __restrict__ Cout,
              int M, int N, int K, int mode)
{
    extern __shared__ unsigned int sm[];

    const int tid  = threadIdx.x;
    const int lane = tid & 31;
    const int warp = tid >> 5;
    const int g    = lane >> 2;
    const int t    = lane & 3;
    const int bm   = blockIdx.y * GBM;
    const int bn   = blockIdx.x * GBN;
    const int wm   = (warp & 1) * 64;
    const int wn   = (warp >> 1) * 32;

    float acc[4][4][4];
    #pragma unroll
    for (int i = 0; i < 4; i++)
        #pragma unroll
        for (int j = 0; j < 4; j++)
            #pragma unroll
            for (int e = 0; e < 4; e++) acc[i][j][e] = 0.0f;

    auto issue = [&](int k0, int s) {
        unsigned int* Asb = sm + s * STAGE_W;
        unsigned int* Bsb = Asb + TILE_W;
        #pragma unroll
        for (int q = 0; q < 4; q++) {                 // A: 128 rows x 8 x 16B
            int item = tid + q * 256;
            int r = item >> 3, c = item & 7;
            cpa16(s2u(Asb + r * RSTR + c * 4), A + (size_t)(bm + r) * K + k0 + c * 8);
        }
        #pragma unroll
        for (int q = 0; q < 4; q++) {                 // B: 128 n-rows x 8 x 16B
            int item = tid + q * 256;
            int r = item >> 3, c = item & 7;
            cpa16(s2u(Bsb + r * RSTR + c * 4), BT + (size_t)(bn + r) * K + k0 + c * 8);
        }
        CP_COMMIT();
    };

    issue(0, 0);
    issue(GBK, 1);

    const int niter = K / GBK;                        // 16
    int s = 0;
    for (int it = 0; it < niter; it++) {
        if (it == niter - 1) cp_wait<0>(); else cp_wait<1>();
        __syncthreads();                              // single barrier per 64-k slab
        if (it + 2 < niter) issue((it + 2) * GBK, (s + 2) % NSTAGE);

        const unsigned int* Asb = sm + s * STAGE_W;
        const unsigned int* Bsb = Asb + TILE_W;

        #pragma unroll
        for (int kk = 0; kk < 4; kk++) {              // four k16 steps per 64-slab
            unsigned int afr[4][4], bfr[4][2];
            #pragma unroll
            for (int mi = 0; mi < 4; mi++) {
                int rb = wm + mi * 16;
                afr[mi][0] = Asb[(rb + g    ) * RSTR + kk * 8 + t    ];
                afr[mi][1] = Asb[(rb + g + 8) * RSTR + kk * 8 + t    ];
                afr[mi][2] = Asb[(rb + g    ) * RSTR + kk * 8 + t + 4];
                afr[mi][3] = Asb[(rb + g + 8) * RSTR + kk * 8 + t + 4];
            }
            #pragma unroll
            for (int ni = 0; ni < 4; ni++) {
                int cb = wn + ni * 8;
                bfr[ni][0] = Bsb[(cb + g) * RSTR + kk * 8 + t    ];
                bfr[ni][1] = Bsb[(cb + g) * RSTR + kk * 8 + t + 4];
            }
            #pragma unroll
            for (int mi = 0; mi < 4; mi++)
                #pragma unroll
                for (int ni = 0; ni < 4; ni++)
                    mma16(acc[mi][ni], afr[mi], bfr[ni]);
        }
        s = (s + 1) % NSTAGE;
    }

    if (mode == 0) {
        float* C = (float*)Cout;
        #pragma unroll
        for (int mi = 0; mi < 4; mi++) {
            #pragma unroll
            for (int ni = 0; ni < 4; ni++) {
                int r0 = bm + wm + mi * 16 + g;
                int c0 = bn + wn + ni * 8 + 2 * t;
                float bx = bias[c0], by = bias[c0 + 1];
                C[(size_t)(r0    ) * N + c0    ] = acc[mi][ni][0] + bx;
                C[(size_t)(r0    ) * N + c0 + 1] = acc[mi][ni][1] + by;
                C[(size_t)(r0 + 8) * N + c0    ] = acc[mi][ni][2] + bx;
                C[(size_t)(r0 + 8) * N + c0 + 1] = acc[mi][ni][3] + by;
            }
        }
    } else {
        __half2* C = (__half2*)Cout;
        #pragma unroll
        for (int mi = 0; mi < 4; mi++) {
            #pragma unroll
            for (int ni = 0; ni < 4; ni++) {
                int r0 = bm + wm + mi * 16 + g;
                int c0 = bn + wn + ni * 8 + 2 * t;
                float sc = (c0 < Dd) ? 0.125f : 1.0f;   // Q pre-scale (exact pow2)
                C[((size_t)(r0    ) * N + c0) >> 1] =
                    __floats2half2_rn(acc[mi][ni][0] * sc, acc[mi][ni][1] * sc);
                C[((size_t)(r0 + 8) * N + c0) >> 1] =
                    __floats2half2_rn(acc[mi][ni][2] * sc, acc[mi][ni][3] * sc);
            }
        }
    }
}

// ---------------- block-sparse flash attention: single-barrier pipeline (R13) ----------------
#define KSTRW 36
#define KBUF_W (128 * KSTRW)                     // 4608 words
#define ATT_SMEM (4 * KBUF_W * 4)                // 73728 B -> 2 CTAs/SM
#define SOFT_C 5.0f
#define L2E 1.44269504f

__global__ __launch_bounds__(256, 2)
void attn_kernel()
{
    extern __shared__ unsigned int sm[];
    unsigned int* kb0 = sm;
    unsigned int* kb1 = sm + KBUF_W;
    unsigned int* vb0 = sm + 2 * KBUF_W;
    unsigned int* vb1 = sm + 3 * KBUF_W;
    __shared__ int live[NB + 1];

    const int qi = NB - 1 - blockIdx.x;          // heavy (high-qi) CTAs first (LPT)
    const int h = blockIdx.y, b = blockIdx.z;
    const int tid  = threadIdx.x;
    const int lane = tid & 31;
    const int warp = tid >> 5;
    const int g    = lane >> 2;
    const int t    = lane & 3;

    if (tid == 0) {
        int n = 0;
        for (int kb = 0; kb < NB; kb++)
            if (!g_mask[qi * NB + kb]) live[n++] = kb;
        live[NB] = n;
    }
    __syncthreads();
    const int nlive = live[NB];

    const __half* Kbase = g_qkv + (size_t)b * Ss * NQKV + Dd + h * HD;
    const __half* Vbase = Kbase + Dd;

    auto issueKV = [&](int kb, unsigned int* kdst, unsigned int* vdst) {
        const __half* ks = Kbase + (size_t)kb * 128 * NQKV;
        const __half* vs = Vbase + (size_t)kb * 128 * NQKV;
        #pragma unroll
        for (int q = 0; q < 4; q++) {                // K: 128 keys x 8 x 16B
            int item = tid + q * 256;
            int key = item >> 3, c = item & 7;
            cpa16(s2u(kdst + key * KSTRW + c * 4), ks + (size_t)key * NQKV + c * 8);
        }
        #pragma unroll
        for (int q = 0; q < 4; q++) {                // V: 128 keys x 8 x 16B
            int item = tid + q * 256;
            int key = item >> 3, c = item & 7;
            cpa16(s2u(vdst + key * KSTRW + c * 4), vs + (size_t)key * NQKV + c * 8);
        }
        CP_COMMIT();
    };

    issueKV(live[0], kb0, vb0);

    // Q a-fragments (fp16, pre-scaled by 0.125), 4 k16 steps over hd=64
    unsigned int qa[4][4];
    {
        int r0 = b * Ss + qi * 128 + warp * 16 + g;
        const unsigned int* q0 = (const unsigned int*)(g_qkv + (size_t)r0 * NQKV + h * HD);
        const unsigned int* q1 = (const unsigned int*)(g_qkv + (size_t)(r0 + 8) * NQKV + h * HD);
        #pragma unroll
        for (int kk = 0; kk < 4; kk++) {
            qa[kk][0] = q0[kk * 8 + t    ];
            qa[kk][1] = q1[kk * 8 + t    ];
            qa[kk][2] = q0[kk * 8 + t + 4];
            qa[kk][3] = q1[kk * 8 + t + 4];
        }
    }

    float o[8][4];
    #pragma unroll
    for (int i = 0; i < 8; i++)
        #pragma unroll
        for (int e = 0; e < 4; e++) o[i][e] = 0.f;
    float lacc[4] = {0.f, 0.f, 0.f, 0.f};        // row-sum accumulator (ones-MMA)

    const unsigned int ones2 = 0x3C003C00u;      // half2(1.0, 1.0)
    unsigned int bones[2] = {ones2, ones2};

    const int keyoff = ((lane >> 3) & 1) * 8 + (lane & 7);
    const int coloff = (lane >> 4) * 8;

    for (int i = 0; i < nlive; i++) {
        const unsigned int* kcur = (i & 1) ? kb1 : kb0;
        unsigned int*       kalt = (i & 1) ? kb0 : kb1;
        const unsigned int* vcur = (i & 1) ? vb1 : vb0;
        unsigned int*       valt = (i & 1) ? vb0 : vb1;
        const bool nx = (i + 1 < nlive);
        const unsigned int vbytes = s2u(vcur);

        cp_wait<0>();
        __syncthreads();                         // K+V(i) ready; all warps done with iter i-1

        if (nx) issueKV(live[i + 1], kalt, valt);   // alt buffers freed by the barrier above

        #pragma unroll
        for (int half = 0; half < 2; half++) {
            const int kb64 = half * 64;

            // ---- S(half) = Q @ K^T over 64 keys, accumulator init -C ----
            float sc[8][4];
            #pragma unroll
            for (int ni = 0; ni < 8; ni++)
                #pragma unroll
                for (int e = 0; e < 4; e++) sc[ni][e] = -SOFT_C;

            #pragma unroll
            for (int kk = 0; kk < 4; kk++) {
                #pragma unroll
                for (int ni = 0; ni < 8; ni++) {
                    unsigned int bb[2];
                    bb[0] = kcur[(kb64 + ni * 8 + g) * KSTRW + kk * 8 + t    ];
                    bb[1] = kcur[(kb64 + ni * 8 + g) * KSTRW + kk * 8 + t + 4];
                    mma16(sc[ni], qa[kk], bb);
                }
            }

            // ---- P = 2^((s-C)*log2e): fp32 FMUL -> half2 -> one ex2.f16x2 per pair ----
            unsigned int p2[8][2];
            #pragma unroll
            for (int ni = 0; ni < 8; ni++) {
                p2[ni][0] = ex2h2(pack2(sc[ni][0] * L2E, sc[ni][1] * L2E));
                p2[ni][1] = ex2h2(pack2(sc[ni][2] * L2E, sc[ni][3] * L2E));
            }

            // ---- O += P @ V, l += P @ ones (V resident since iter top) ----
            #pragma unroll
            for (int kk = 0; kk < 4; kk++) {
                unsigned int pa[4];
                pa[0] = p2[2 * kk    ][0];
                pa[1] = p2[2 * kk    ][1];
                pa[2] = p2[2 * kk + 1][0];
                pa[3] = p2[2 * kk + 1][1];
                mma16(lacc, pa, bones);          // row sums of the SAME fp16 P
                #pragma unroll
                for (int cp = 0; cp < 4; cp++) {
                    unsigned int r0, r1, r2, r3;
                    unsigned int addr = vbytes
                        + (unsigned int)((kb64 + kk * 16 + keyoff) * (KSTRW * 4)
                                         + (cp * 16 + coloff) * 2);
                    ldmx4t(r0, r1, r2, r3, addr);
                    unsigned int bb[2];
                    bb[0] = r0; bb[1] = r1; mma16(o[cp * 2    ], pa, bb);
                    bb[0] = r2; bb[1] = r3; mma16(o[cp * 2 + 1], pa, bb);
                }
            }
        }
    }

    // ---- epilogue: normalize by l, store fp16 for the proj GEMM ----
    float inv0 = 1.0f / lacc[0], inv1 = 1.0f / lacc[2];
    int r0 = qi * 128 + warp * 16 + g;
    __half2* dst0 = (__half2*)(g_att + (size_t)(r0 + b * Ss) * Dd + h * HD);
    __half2* dst1 = (__half2*)(g_att + (size_t)(r0 + 8 + b * Ss) * Dd + h * HD);
    #pragma unroll
    for (int ni = 0; ni < 8; ni++) {
        int cw = (ni * 8 + 2 * t) >> 1;
        dst0[cw] = __floats2half2_rn(o[ni][0] * inv0, o[ni][1] * inv0);
        dst1[cw] = __floats2half2_rn(o[ni][2] * inv1, o[ni][3] * inv1);
    }
}

// ---------------- launch ----------------
// 4 launches; ncu-profiled slot (index 3) = proj GEMM (watch tensor% vs R13's 38.7).
extern "C" void kernel_launch(void* const* d_in, const int* in_sizes, int n_in,
                              void* d_out, int out_size)
{
    const float*         x      = (const float*)d_in[0];
    const float*         w_qkv  = (const float*)d_in[1];
    const float*         w_proj = (const float*)d_in[2];
    const float*         b_proj = (const float*)d_in[3];
    const unsigned char* bmask  = (const unsigned char*)d_in[4];
    float*               out    = (float*)d_out;

    (void)in_sizes; (void)n_in; (void)out_size;

    cudaFuncSetAttribute(gemm_f16,    cudaFuncAttributeMaxDynamicSharedMemorySize, GEMM_SMEM);
    cudaFuncSetAttribute(attn_kernel, cudaFuncAttributeMaxDynamicSharedMemorySize, ATT_SMEM);

    void *p_x, *p_wqkvT, *p_wprojT, *p_qkv, *p_att;
    cudaGetSymbolAddress(&p_x,      g_x);
    cudaGetSymbolAddress(&p_wqkvT,  g_wqkvT);
    cudaGetSymbolAddress(&p_wprojT, g_wprojT);
    cudaGetSymbolAddress(&p_qkv,    g_qkv);
    cudaGetSymbolAddress(&p_att,    g_att);

    prepass<<<CONV_BLKS + TR_BX * TR_BY, 256>>>(x, bmask, w_qkv, w_proj);             // 0

    // 1: QKV [4096,1024] @ [1024,3072] -> fp16 (Q scaled 0.125)
    gemm_f16<<<dim3(NQKV / GBN, ROWS / GBM), 256, GEMM_SMEM>>>(
        (const __half*)p_x, (const __half*)p_wqkvT, nullptr, p_qkv,
        ROWS, NQKV, Dd, 1);

    attn_kernel<<<dim3(NB, Hh, Bb), 256, ATT_SMEM>>>();                               // 2

    // 3 (profiled): proj [4096,1024] @ [1024,1024] + bias -> float out
    gemm_f16<<<dim3(Dd / GBN, ROWS / GBM), 256, GEMM_SMEM>>>(
        (const __half*)p_att, (const __half*)p_wprojT, b_proj, out,
        ROWS, Dd, Dd, 0);
}

// round 15
// speedup vs baseline: 1.0191x; 1.0191x over previous
#include <cuda_runtime.h>
#include <cuda_fp16.h>

// ---------------- problem constants ----------------
#define Bb   2
#define Ss   2048
#define Dd   1024
#define Hh   16
#define HD   64
#define NB   16
#define ROWS 4096        // B*S
#define NQKV 3072        // 3*D

// ---------------- device scratch (fp16) ----------------
__device__ __half g_x     [ROWS * Dd];     // x, [4096][1024] K-contig
__device__ __half g_wqkvT [NQKV * Dd];     // w_qkv^T, [3072][1024] K-contig (n-major)
__device__ __half g_wprojT[Dd * Dd];       // w_proj^T, [1024][1024] K-contig
__device__ __half g_qkv   [ROWS * NQKV];   // QKV out (Q pre-scaled by 0.125*log2e)
__device__ __half g_att   [ROWS * Dd];     // attention out
__device__ int    g_mask  [NB * NB];

// ---------------- helpers ----------------
__device__ __forceinline__ unsigned int pack2(float a, float b) {
    __half2 h = __floats2half2_rn(a, b);       // low = a (even col), high = b
    return *(unsigned int*)&h;
}
__device__ __forceinline__ unsigned int ex2h2(unsigned int h2) {
    unsigned int r;
    asm("ex2.approx.f16x2 %0, %1;" : "=r"(r) : "r"(h2));   // 2^x both halves, one MUFU op
    return r;
}
__device__ __forceinline__ void mma16(float* c, const unsigned int* a, const unsigned int* b) {
    asm volatile(
        "mma.sync.aligned.m16n8k16.row.col.f32.f16.f16.f32 "
        "{%0,%1,%2,%3}, {%4,%5,%6,%7}, {%8,%9}, {%0,%1,%2,%3};"
        : "+f"(c[0]), "+f"(c[1]), "+f"(c[2]), "+f"(c[3])
        : "r"(a[0]), "r"(a[1]), "r"(a[2]), "r"(a[3]), "r"(b[0]), "r"(b[1]));
}
__device__ __forceinline__ unsigned int s2u(const void* p) {
    return (unsigned int)__cvta_generic_to_shared(p);
}
__device__ __forceinline__ void cpa16(unsigned int s, const void* g) {
    asm volatile("cp.async.cg.shared.global [%0], [%1], 16;" :: "r"(s), "l"(g));
}
#define CP_COMMIT() asm volatile("cp.async.commit_group;")
template<int N> __device__ __forceinline__ void cp_wait() {
    asm volatile("cp.async.wait_group %0;" :: "n"(N));
}
__device__ __forceinline__ void ldmx4t(unsigned int& r0, unsigned int& r1,
                                       unsigned int& r2, unsigned int& r3, unsigned int addr) {
    asm volatile("ldmatrix.sync.aligned.m8n8.x4.trans.shared.b16 {%0,%1,%2,%3}, [%4];"
                 : "=r"(r0), "=r"(r1), "=r"(r2), "=r"(r3) : "r"(addr));
}

// ---------------- x -> fp16, mask canonicalization fused ----------------
__global__ void convert_x_mask(const float* __restrict__ x, const unsigned char* __restrict__ raw) {
    if (blockIdx.x == 0 && threadIdx.x == 0) {
        const unsigned int* w = (const unsigned int*)raw;
        bool all01 = true, allf = true;
        for (int i = 0; i < 64; i++) {
            unsigned int v = w[i];
            if (v != 0u && v != 1u) all01 = false;
            if (v != 0u && v != 0x3F800000u) allf = false;
        }
        if (all01)      for (int i = 0; i < 256; i++) g_mask[i] = (int)w[i];
        else if (allf)  for (int i = 0; i < 256; i++) g_mask[i] = (w[i] != 0u) ? 1 : 0;
        else            for (int i = 0; i < 256; i++) g_mask[i] = raw[i] ? 1 : 0;
    }
    int n4 = ROWS * Dd / 4;
    for (int i = blockIdx.x * blockDim.x + threadIdx.x; i < n4; i += gridDim.x * blockDim.x) {
        float4 v = ((const float4*)x)[i];
        uint2 o;
        o.x = pack2(v.x, v.y);
        o.y = pack2(v.z, v.w);
        ((uint2*)g_x)[i] = o;
    }
}

// ---------------- fused transpose: w_qkv and w_proj -> fp16 [N,K] ----------------
__global__ void transpose_fused(const float* __restrict__ wq, const float* __restrict__ wp) {
    __shared__ float tl[32][33];
    int bx = blockIdx.x;
    const float* src; __half* dst; int Nn; int n0;
    if (bx < NQKV / 32) { src = wq; dst = g_wqkvT;  Nn = NQKV; n0 = bx * 32; }
    else                { src = wp; dst = g_wprojT; Nn = Dd;   n0 = (bx - NQKV / 32) * 32; }
    int k0 = blockIdx.y * 32;
    int tx = threadIdx.x, ty = threadIdx.y;      // 32 x 8
    #pragma unroll
    for (int i = 0; i < 32; i += 8)
        tl[ty + i][tx] = src[(size_t)(k0 + ty + i) * Nn + n0 + tx];
    __syncthreads();
    #pragma unroll
    for (int i = 0; i < 32; i += 8)
        dst[(size_t)(n0 + ty + i) * Dd + k0 + tx] = __float2half_rn(tl[tx][ty + i]);
}

// ---------------- fp16 GEMM (exact R9/R12 config: 128x128x64, occ 2 - best known) ----------------
#define GBM 128
#define GBN 128
#define GBK 64
#define RSTR 36
#define TILE_W (128 * RSTR)          // 4608 words
#define STAGE_W (2 * TILE_W)         // 9216 words = 36 KB
#define NSTAGE 3
#define GEMM_SMEM (NSTAGE * STAGE_W * 4)   // 110592 B -> 2 CTAs/SM

// Q columns pre-scaled by 0.125 * log2(e): S' = s*log2e comes out of the S-MMA,
// so the attention exp stage needs ZERO multiplies (just pack + ex2).
#define QSCALE 0.18033688f

__global__ __launch_bounds__(256, 2)
void gemm_f16(const __half* __restrict__ A, const __half* __restrict__ BT,
              const float* __restrict__ bias, void* __restrict__ Cout,
              int M, int N, int K, int mode)
{
    extern __shared__ unsigned int sm[];

    const int tid  = threadIdx.x;
    const int lane = tid & 31;
    const int warp = tid >> 5;
    const int g    = lane >> 2;
    const int t    = lane & 3;
    const int bm   = blockIdx.y * GBM;
    const int bn   = blockIdx.x * GBN;
    const int wm   = (warp & 1) * 64;
    const int wn   = (warp >> 1) * 32;

    float acc[4][4][4];
    #pragma unroll
    for (int i = 0; i < 4; i++)
        #pragma unroll
        for (int j = 0; j < 4; j++)
            #pragma unroll
            for (int e = 0; e < 4; e++) acc[i][j][e] = 0.0f;

    auto issue = [&](int k0, int s) {
        unsigned int* Asb = sm + s * STAGE_W;
        unsigned int* Bsb = Asb + TILE_W;
        #pragma unroll
        for (int q = 0; q < 4; q++) {                 // A: 128 rows x 8 x 16B
            int item = tid + q * 256;
            int r = item >> 3, c = item & 7;
            cpa16(s2u(Asb + r * RSTR + c * 4), A + (size_t)(bm + r) * K + k0 + c * 8);
        }
        #pragma unroll
        for (int q = 0; q < 4; q++) {                 // B: 128 n-rows x 8 x 16B
            int item = tid + q * 256;
            int r = item >> 3, c = item & 7;
            cpa16(s2u(Bsb + r * RSTR + c * 4), BT + (size_t)(bn + r) * K + k0 + c * 8);
        }
        CP_COMMIT();
    };

    issue(0, 0);
    issue(GBK, 1);

    const int niter = K / GBK;                        // 16
    int s = 0;
    for (int it = 0; it < niter; it++) {
        if (it == niter - 1) cp_wait<0>(); else cp_wait<1>();
        __syncthreads();                              // single barrier per 64-k slab
        if (it + 2 < niter) issue((it + 2) * GBK, (s + 2) % NSTAGE);

        const unsigned int* Asb = sm + s * STAGE_W;
        const unsigned int* Bsb = Asb + TILE_W;

        #pragma unroll
        for (int kk = 0; kk < 4; kk++) {              // four k16 steps per 64-slab
            unsigned int afr[4][4], bfr[4][2];
            #pragma unroll
            for (int mi = 0; mi < 4; mi++) {
                int rb = wm + mi * 16;
                afr[mi][0] = Asb[(rb + g    ) * RSTR + kk * 8 + t    ];
                afr[mi][1] = Asb[(rb + g + 8) * RSTR + kk * 8 + t    ];
                afr[mi][2] = Asb[(rb + g    ) * RSTR + kk * 8 + t + 4];
                afr[mi][3] = Asb[(rb + g + 8) * RSTR + kk * 8 + t + 4];
            }
            #pragma unroll
            for (int ni = 0; ni < 4; ni++) {
                int cb = wn + ni * 8;
                bfr[ni][0] = Bsb[(cb + g) * RSTR + kk * 8 + t    ];
                bfr[ni][1] = Bsb[(cb + g) * RSTR + kk * 8 + t + 4];
            }
            #pragma unroll
            for (int mi = 0; mi < 4; mi++)
                #pragma unroll
                for (int ni = 0; ni < 4; ni++)
                    mma16(acc[mi][ni], afr[mi], bfr[ni]);
        }
        s = (s + 1) % NSTAGE;
    }

    if (mode == 0) {
        float* C = (float*)Cout;
        #pragma unroll
        for (int mi = 0; mi < 4; mi++) {
            #pragma unroll
            for (int ni = 0; ni < 4; ni++) {
                int r0 = bm + wm + mi * 16 + g;
                int c0 = bn + wn + ni * 8 + 2 * t;
                float bx = bias[c0], by = bias[c0 + 1];
                C[(size_t)(r0    ) * N + c0    ] = acc[mi][ni][0] + bx;
                C[(size_t)(r0    ) * N + c0 + 1] = acc[mi][ni][1] + by;
                C[(size_t)(r0 + 8) * N + c0    ] = acc[mi][ni][2] + bx;
                C[(size_t)(r0 + 8) * N + c0 + 1] = acc[mi][ni][3] + by;
            }
        }
    } else {
        __half2* C = (__half2*)Cout;
        #pragma unroll
        for (int mi = 0; mi < 4; mi++) {
            #pragma unroll
            for (int ni = 0; ni < 4; ni++) {
                int r0 = bm + wm + mi * 16 + g;
                int c0 = bn + wn + ni * 8 + 2 * t;
                float sc = (c0 < Dd) ? QSCALE : 1.0f;   // Q pre-scale includes log2e
                C[((size_t)(r0    ) * N + c0) >> 1] =
                    __floats2half2_rn(acc[mi][ni][0] * sc, acc[mi][ni][1] * sc);
                C[((size_t)(r0 + 8) * N + c0) >> 1] =
                    __floats2half2_rn(acc[mi][ni][2] * sc, acc[mi][ni][3] * sc);
            }
        }
    }
}

// ---------------- block-sparse flash attention (R12 structure, zero-FMUL exp) ----------------
// S' = s*log2e from the MMA directly (Q pre-scaled); accumulator init -5*log2e;
// P = ex2(S') with ONE ex2.approx.f16x2 per pair and NO multiplies.
// l via ones-column MMA on the same fp16 P. 2 CTAs/SM.
#define KSTRW 36
#define KBUF_W (128 * KSTRW)                     // 4608 words
#define ATT_SMEM (4 * KBUF_W * 4)                // 73728 B -> 2 CTAs/SM
#define SOFT_CL2E 7.2134752f                     // 5 * log2(e)

__global__ __launch_bounds__(256, 2)
void attn_kernel()
{
    extern __shared__ unsigned int sm[];
    unsigned int* kb0 = sm;
    unsigned int* kb1 = sm + KBUF_W;
    unsigned int* vb0 = sm + 2 * KBUF_W;
    unsigned int* vb1 = sm + 3 * KBUF_W;
    __shared__ int live[NB + 1];

    const int qi = NB - 1 - blockIdx.x;          // heavy (high-qi) CTAs first (LPT)
    const int h = blockIdx.y, b = blockIdx.z;
    const int tid  = threadIdx.x;
    const int lane = tid & 31;
    const int warp = tid >> 5;
    const int g    = lane >> 2;
    const int t    = lane & 3;

    if (tid == 0) {
        int n = 0;
        for (int kb = 0; kb < NB; kb++)
            if (!g_mask[qi * NB + kb]) live[n++] = kb;
        live[NB] = n;
    }
    __syncthreads();
    const int nlive = live[NB];

    const __half* Kbase = g_qkv + (size_t)b * Ss * NQKV + Dd + h * HD;
    const __half* Vbase = Kbase + Dd;

    auto issueT = [&](const __half* base, int kb, unsigned int* dst) {
        const __half* src = base + (size_t)kb * 128 * NQKV;
        #pragma unroll
        for (int q = 0; q < 4; q++) {                // 128 keys x 8 x 16B
            int item = tid + q * 256;
            int key = item >> 3, c = item & 7;
            cpa16(s2u(dst + key * KSTRW + c * 4), src + (size_t)key * NQKV + c * 8);
        }
        CP_COMMIT();
    };

    issueT(Kbase, live[0], kb0);
    issueT(Vbase, live[0], vb0);

    // Q a-fragments (fp16, pre-scaled by 0.125*log2e), 4 k16 steps over hd=64
    unsigned int qa[4][4];
    {
        int r0 = b * Ss + qi * 128 + warp * 16 + g;
        const unsigned int* q0 = (const unsigned int*)(g_qkv + (size_t)r0 * NQKV + h * HD);
        const unsigned int* q1 = (const unsigned int*)(g_qkv + (size_t)(r0 + 8) * NQKV + h * HD);
        #pragma unroll
        for (int kk = 0; kk < 4; kk++) {
            qa[kk][0] = q0[kk * 8 + t    ];
            qa[kk][1] = q1[kk * 8 + t    ];
            qa[kk][2] = q0[kk * 8 + t + 4];
            qa[kk][3] = q1[kk * 8 + t + 4];
        }
    }

    float o[8][4];
    #pragma unroll
    for (int i = 0; i < 8; i++)
        #pragma unroll
        for (int e = 0; e < 4; e++) o[i][e] = 0.f;
    float lacc[4] = {0.f, 0.f, 0.f, 0.f};        // row-sum accumulator (ones-MMA)

    const unsigned int ones2 = 0x3C003C00u;      // half2(1.0, 1.0)
    unsigned int bones[2] = {ones2, ones2};

    const int keyoff = ((lane >> 3) & 1) * 8 + (lane & 7);
    const int coloff = (lane >> 4) * 8;

    for (int i = 0; i < nlive; i++) {
        const unsigned int* kcur = (i & 1) ? kb1 : kb0;
        unsigned int*       kalt = (i & 1) ? kb0 : kb1;
        const unsigned int* vcur = (i & 1) ? vb1 : vb0;
        unsigned int*       valt = (i & 1) ? vb0 : vb1;
        const bool nx = (i + 1 < nlive);
        const unsigned int vbytes = s2u(vcur);

        cp_wait<1>();
        __syncthreads();                         // K(i) ready; prior iter fully done

        #pragma unroll
        for (int half = 0; half < 2; half++) {
            const int kb64 = half * 64;

            // ---- S'(half) = Q' @ K^T over 64 keys, accumulator init -C*log2e ----
            float sc[8][4];
            #pragma unroll
            for (int ni = 0; ni < 8; ni++)
                #pragma unroll
                for (int e = 0; e < 4; e++) sc[ni][e] = -SOFT_CL2E;

            #pragma unroll
            for (int kk = 0; kk < 4; kk++) {
                #pragma unroll
                for (int ni = 0; ni < 8; ni++) {
                    unsigned int bb[2];
                    bb[0] = kcur[(kb64 + ni * 8 + g) * KSTRW + kk * 8 + t    ];
                    bb[1] = kcur[(kb64 + ni * 8 + g) * KSTRW + kk * 8 + t + 4];
                    mma16(sc[ni], qa[kk], bb);
                }
            }

            if (half == 0 && nx) issueT(Kbase, live[i + 1], kalt);

            // ---- P = 2^(S'): pack + one ex2.f16x2 per pair, ZERO multiplies ----
            unsigned int p2[8][2];
            #pragma unroll
            for (int ni = 0; ni < 8; ni++) {
                p2[ni][0] = ex2h2(pack2(sc[ni][0], sc[ni][1]));
                p2[ni][1] = ex2h2(pack2(sc[ni][2], sc[ni][3]));
            }

            if (half == 0) {
                if (nx) cp_wait<1>(); else cp_wait<0>();
                __syncthreads();                 // V(i) ready
            }

            // ---- O += P @ V, l += P @ ones ----
            #pragma unroll
            for (int kk = 0; kk < 4; kk++) {
                unsigned int pa[4];
                pa[0] = p2[2 * kk    ][0];
                pa[1] = p2[2 * kk    ][1];
                pa[2] = p2[2 * kk + 1][0];
                pa[3] = p2[2 * kk + 1][1];
                mma16(lacc, pa, bones);          // row sums of the SAME fp16 P
                #pragma unroll
                for (int cp = 0; cp < 4; cp++) {
                    unsigned int r0, r1, r2, r3;
                    unsigned int addr = vbytes
                        + (unsigned int)((kb64 + kk * 16 + keyoff) * (KSTRW * 4)
                                         + (cp * 16 + coloff) * 2);
                    ldmx4t(r0, r1, r2, r3, addr);
                    unsigned int bb[2];
                    bb[0] = r0; bb[1] = r1; mma16(o[cp * 2    ], pa, bb);
                    bb[0] = r2; bb[1] = r3; mma16(o[cp * 2 + 1], pa, bb);
                }
            }
        }

        if (nx) issueT(Vbase, live[i + 1], valt);
    }

    // ---- epilogue: normalize by l, store fp16 for the proj GEMM ----
    float inv0 = 1.0f / lacc[0], inv1 = 1.0f / lacc[2];
    int r0 = qi * 128 + warp * 16 + g;
    __half2* dst0 = (__half2*)(g_att + (size_t)(r0 + b * Ss) * Dd + h * HD);
    __half2* dst1 = (__half2*)(g_att + (size_t)(r0 + 8 + b * Ss) * Dd + h * HD);
    #pragma unroll
    for (int ni = 0; ni < 8; ni++) {
        int cw = (ni * 8 + 2 * t) >> 1;
        dst0[cw] = __floats2half2_rn(o[ni][0] * inv0, o[ni][1] * inv0);
        dst1[cw] = __floats2half2_rn(o[ni][2] * inv1, o[ni][3] * inv1);
    }
}

// ---------------- launch ----------------
// 5 launches; ncu-profiled slot (index 3) = attn_kernel (watch fma% vs R12's 3.9).
extern "C" void kernel_launch(void* const* d_in, const int* in_sizes, int n_in,
                              void* d_out, int out_size)
{
    const float*         x      = (const float*)d_in[0];
    const float*         w_qkv  = (const float*)d_in[1];
    const float*         w_proj = (const float*)d_in[2];
    const float*         b_proj = (const float*)d_in[3];
    const unsigned char* bmask  = (const unsigned char*)d_in[4];
    float*               out    = (float*)d_out;

    (void)in_sizes; (void)n_in; (void)out_size;

    cudaFuncSetAttribute(gemm_f16,    cudaFuncAttributeMaxDynamicSharedMemorySize, GEMM_SMEM);
    cudaFuncSetAttribute(attn_kernel, cudaFuncAttributeMaxDynamicSharedMemorySize, ATT_SMEM);

    void *p_x, *p_wqkvT, *p_wprojT, *p_qkv, *p_att;
    cudaGetSymbolAddress(&p_x,      g_x);
    cudaGetSymbolAddress(&p_wqkvT,  g_wqkvT);
    cudaGetSymbolAddress(&p_wprojT, g_wprojT);
    cudaGetSymbolAddress(&p_qkv,    g_qkv);
    cudaGetSymbolAddress(&p_att,    g_att);

    convert_x_mask<<<1184, 256>>>(x, bmask);                                          // 0
    transpose_fused<<<dim3(NQKV / 32 + Dd / 32, Dd / 32), dim3(32, 8)>>>(w_qkv, w_proj); // 1

    // 2: QKV [4096,1024] @ [1024,3072] -> fp16 (Q scaled 0.125*log2e)
    gemm_f16<<<dim3(NQKV / GBN, ROWS / GBM), 256, GEMM_SMEM>>>(
        (const __half*)p_x, (const __half*)p_wqkvT, nullptr, p_qkv,
        ROWS, NQKV, Dd, 1);

    attn_kernel<<<dim3(NB, Hh, Bb), 256, ATT_SMEM>>>();                               // 3 (profiled)

    // 4: proj [4096,1024] @ [1024,1024] + bias -> float out
    gemm_f16<<<dim3(Dd / GBN, ROWS / GBM), 256, GEMM_SMEM>>>(
        (const __half*)p_att, (const __half*)p_wprojT, b_proj, out,
        ROWS, Dd, Dd, 0);
}

// round 16
// speedup vs baseline: 1.0543x; 1.0345x over previous
#include <cuda_runtime.h>
#include <cuda_fp16.h>

// ---------------- problem constants ----------------
#define Bb   2
#define Ss   2048
#define Dd   1024
#define Hh   16
#define HD   64
#define NB   16
#define ROWS 4096        // B*S
#define NQKV 3072        // 3*D
#define NJOBS (NB * Hh * Bb)   // 512 attention jobs

// ---------------- device scratch (fp16) ----------------
__device__ __half g_x     [ROWS * Dd];
__device__ __half g_wqkvT [NQKV * Dd];
__device__ __half g_wprojT[Dd * Dd];
__device__ __half g_qkv   [ROWS * NQKV];   // QKV out (Q pre-scaled by 0.125*log2e)
__device__ __half g_att   [ROWS * Dd];
__device__ int    g_mask  [NB * NB];
__device__ unsigned int g_ctr;             // attention job counter (reset in convert_x_mask)

// ---------------- helpers ----------------
__device__ __forceinline__ unsigned int pack2(float a, float b) {
    __half2 h = __floats2half2_rn(a, b);
    return *(unsigned int*)&h;
}
__device__ __forceinline__ unsigned int ex2h2(unsigned int h2) {
    unsigned int r;
    asm("ex2.approx.f16x2 %0, %1;" : "=r"(r) : "r"(h2));
    return r;
}
__device__ __forceinline__ void mma16(float* c, const unsigned int* a, const unsigned int* b) {
    asm volatile(
        "mma.sync.aligned.m16n8k16.row.col.f32.f16.f16.f32 "
        "{%0,%1,%2,%3}, {%4,%5,%6,%7}, {%8,%9}, {%0,%1,%2,%3};"
        : "+f"(c[0]), "+f"(c[1]), "+f"(c[2]), "+f"(c[3])
        : "r"(a[0]), "r"(a[1]), "r"(a[2]), "r"(a[3]), "r"(b[0]), "r"(b[1]));
}
__device__ __forceinline__ unsigned int s2u(const void* p) {
    return (unsigned int)__cvta_generic_to_shared(p);
}
__device__ __forceinline__ void cpa16(unsigned int s, const void* g) {
    asm volatile("cp.async.cg.shared.global [%0], [%1], 16;" :: "r"(s), "l"(g));
}
#define CP_COMMIT() asm volatile("cp.async.commit_group;")
template<int N> __device__ __forceinline__ void cp_wait() {
    asm volatile("cp.async.wait_group %0;" :: "n"(N));
}
__device__ __forceinline__ void ldmx4t(unsigned int& r0, unsigned int& r1,
                                       unsigned int& r2, unsigned int& r3, unsigned int addr) {
    asm volatile("ldmatrix.sync.aligned.m8n8.x4.trans.shared.b16 {%0,%1,%2,%3}, [%4];"
                 : "=r"(r0), "=r"(r1), "=r"(r2), "=r"(r3) : "r"(addr));
}

// ---------------- x -> fp16, mask canon, job-counter reset ----------------
__global__ void convert_x_mask(const float* __restrict__ x, const unsigned char* __restrict__ raw) {
    if (blockIdx.x == 0 && threadIdx.x == 0) {
        g_ctr = 0;                                   // reset work-steal counter every replay
        const unsigned int* w = (const unsigned int*)raw;
        bool all01 = true, allf = true;
        for (int i = 0; i < 64; i++) {
            unsigned int v = w[i];
            if (v != 0u && v != 1u) all01 = false;
            if (v != 0u && v != 0x3F800000u) allf = false;
        }
        if (all01)      for (int i = 0; i < 256; i++) g_mask[i] = (int)w[i];
        else if (allf)  for (int i = 0; i < 256; i++) g_mask[i] = (w[i] != 0u) ? 1 : 0;
        else            for (int i = 0; i < 256; i++) g_mask[i] = raw[i] ? 1 : 0;
    }
    int n4 = ROWS * Dd / 4;
    for (int i = blockIdx.x * blockDim.x + threadIdx.x; i < n4; i += gridDim.x * blockDim.x) {
        float4 v = ((const float4*)x)[i];
        uint2 o;
        o.x = pack2(v.x, v.y);
        o.y = pack2(v.z, v.w);
        ((uint2*)g_x)[i] = o;
    }
}

// ---------------- fused transpose: w_qkv and w_proj -> fp16 [N,K] ----------------
__global__ void transpose_fused(const float* __restrict__ wq, const float* __restrict__ wp) {
    __shared__ float tl[32][33];
    int bx = blockIdx.x;
    const float* src; __half* dst; int Nn; int n0;
    if (bx < NQKV / 32) { src = wq; dst = g_wqkvT;  Nn = NQKV; n0 = bx * 32; }
    else                { src = wp; dst = g_wprojT; Nn = Dd;   n0 = (bx - NQKV / 32) * 32; }
    int k0 = blockIdx.y * 32;
    int tx = threadIdx.x, ty = threadIdx.y;      // 32 x 8
    #pragma unroll
    for (int i = 0; i < 32; i += 8)
        tl[ty + i][tx] = src[(size_t)(k0 + ty + i) * Nn + n0 + tx];
    __syncthreads();
    #pragma unroll
    for (int i = 0; i < 32; i += 8)
        dst[(size_t)(n0 + ty + i) * Dd + k0 + tx] = __float2half_rn(tl[tx][ty + i]);
}

// ---------------- fp16 GEMM (exact R9/R12/R15 config: 128x128x64, occ 2) ----------------
#define GBM 128
#define GBN 128
#define GBK 64
#define RSTR 36
#define TILE_W (128 * RSTR)
#define STAGE_W (2 * TILE_W)
#define NSTAGE 3
#define GEMM_SMEM (NSTAGE * STAGE_W * 4)

#define QSCALE 0.18033688f                   // 0.125 * log2(e)

__global__ __launch_bounds__(256, 2)
void gemm_f16(const __half* __restrict__ A, const __half* __restrict__ BT,
              const float* __restrict__ bias, void* __restrict__ Cout,
              int M, int N, int K, int mode)
{
    extern __shared__ unsigned int sm[];

    const int tid  = threadIdx.x;
    const int lane = tid & 31;
    const int warp = tid >> 5;
    const int g    = lane >> 2;
    const int t    = lane & 3;
    const int bm   = blockIdx.y * GBM;
    const int bn   = blockIdx.x * GBN;
    const int wm   = (warp & 1) * 64;
    const int wn   = (warp >> 1) * 32;

    float acc[4][4][4];
    #pragma unroll
    for (int i = 0; i < 4; i++)
        #pragma unroll
        for (int j = 0; j < 4; j++)
            #pragma unroll
            for (int e = 0; e < 4; e++) acc[i][j][e] = 0.0f;

    auto issue = [&](int k0, int s) {
        unsigned int* Asb = sm + s * STAGE_W;
        unsigned int* Bsb = Asb + TILE_W;
        #pragma unroll
        for (int q = 0; q < 4; q++) {
            int item = tid + q * 256;
            int r = item >> 3, c = item & 7;
            cpa16(s2u(Asb + r * RSTR + c * 4), A + (size_t)(bm + r) * K + k0 + c * 8);
        }
        #pragma unroll
        for (int q = 0; q < 4; q++) {
            int item = tid + q * 256;
            int r = item >> 3, c = item & 7;
            cpa16(s2u(Bsb + r * RSTR + c * 4), BT + (size_t)(bn + r) * K + k0 + c * 8);
        }
        CP_COMMIT();
    };

    issue(0, 0);
    issue(GBK, 1);

    const int niter = K / GBK;
    int s = 0;
    for (int it = 0; it < niter; it++) {
        if (it == niter - 1) cp_wait<0>(); else cp_wait<1>();
        __syncthreads();
        if (it + 2 < niter) issue((it + 2) * GBK, (s + 2) % NSTAGE);

        const unsigned int* Asb = sm + s * STAGE_W;
        const unsigned int* Bsb = Asb + TILE_W;

        #pragma unroll
        for (int kk = 0; kk < 4; kk++) {
            unsigned int afr[4][4], bfr[4][2];
            #pragma unroll
            for (int mi = 0; mi < 4; mi++) {
                int rb = wm + mi * 16;
                afr[mi][0] = Asb[(rb + g    ) * RSTR + kk * 8 + t    ];
                afr[mi][1] = Asb[(rb + g + 8) * RSTR + kk * 8 + t    ];
                afr[mi][2] = Asb[(rb + g    ) * RSTR + kk * 8 + t + 4];
                afr[mi][3] = Asb[(rb + g + 8) * RSTR + kk * 8 + t + 4];
            }
            #pragma unroll
            for (int ni = 0; ni < 4; ni++) {
                int cb = wn + ni * 8;
                bfr[ni][0] = Bsb[(cb + g) * RSTR + kk * 8 + t    ];
                bfr[ni][1] = Bsb[(cb + g) * RSTR + kk * 8 + t + 4];
            }
            #pragma unroll
            for (int mi = 0; mi < 4; mi++)
                #pragma unroll
                for (int ni = 0; ni < 4; ni++)
                    mma16(acc[mi][ni], afr[mi], bfr[ni]);
        }
        s = (s + 1) % NSTAGE;
    }

    if (mode == 0) {
        float* C = (float*)Cout;
        #pragma unroll
        for (int mi = 0; mi < 4; mi++) {
            #pragma unroll
            for (int ni = 0; ni < 4; ni++) {
                int r0 = bm + wm + mi * 16 + g;
                int c0 = bn + wn + ni * 8 + 2 * t;
                float bx = bias[c0], by = bias[c0 + 1];
                C[(size_t)(r0    ) * N + c0    ] = acc[mi][ni][0] + bx;
                C[(size_t)(r0    ) * N + c0 + 1] = acc[mi][ni][1] + by;
                C[(size_t)(r0 + 8) * N + c0    ] = acc[mi][ni][2] + bx;
                C[(size_t)(r0 + 8) * N + c0 + 1] = acc[mi][ni][3] + by;
            }
        }
    } else {
        __half2* C = (__half2*)Cout;
        #pragma unroll
        for (int mi = 0; mi < 4; mi++) {
            #pragma unroll
            for (int ni = 0; ni < 4; ni++) {
                int r0 = bm + wm + mi * 16 + g;
                int c0 = bn + wn + ni * 8 + 2 * t;
                float sc = (c0 < Dd) ? QSCALE : 1.0f;
                C[((size_t)(r0    ) * N + c0) >> 1] =
                    __floats2half2_rn(acc[mi][ni][0] * sc, acc[mi][ni][1] * sc);
                C[((size_t)(r0 + 8) * N + c0) >> 1] =
                    __floats2half2_rn(acc[mi][ni][2] * sc, acc[mi][ni][3] * sc);
            }
        }
    }
}

// ---------------- persistent work-stealing block-sparse flash attention ----------------
// Jobs (qi,h,b) grabbed via global atomic in descending-work (LPT) order:
// qi = 15 - (j>>5). Per-job math identical to R15 -> bit-identical output.
#define KSTRW 36
#define KBUF_W (128 * KSTRW)
#define ATT_SMEM (4 * KBUF_W * 4)                // 73728 B -> 2 CTAs/SM
#define SOFT_CL2E 7.2134752f                     // 5 * log2(e)

__global__ __launch_bounds__(256, 2)
void attn_kernel()
{
    extern __shared__ unsigned int sm[];
    unsigned int* kb0 = sm;
    unsigned int* kb1 = sm + KBUF_W;
    unsigned int* vb0 = sm + 2 * KBUF_W;
    unsigned int* vb1 = sm + 3 * KBUF_W;
    __shared__ int live[NB + 1];
    __shared__ int jobv;

    const int tid  = threadIdx.x;
    const int lane = tid & 31;
    const int warp = tid >> 5;
    const int g    = lane >> 2;
    const int t    = lane & 3;

    const int keyoff = ((lane >> 3) & 1) * 8 + (lane & 7);
    const int coloff = (lane >> 4) * 8;
    const unsigned int ones2 = 0x3C003C00u;
    unsigned int bones[2] = {ones2, ones2};

    for (;;) {
        // ---- grab next job (LPT order) ----
        if (tid == 0) jobv = (int)atomicAdd(&g_ctr, 1u);
        __syncthreads();
        const int j = jobv;
        if (j >= NJOBS) break;                       // uniform across CTA

        const int qi = NB - 1 - (j >> 5);            // heaviest first
        const int h  = j & 15;
        const int b  = (j >> 4) & 1;

        if (tid == 0) {
            int n = 0;
            for (int kb = 0; kb < NB; kb++)
                if (!g_mask[qi * NB + kb]) live[n++] = kb;
            live[NB] = n;
        }
        __syncthreads();
        const int nlive = live[NB];

        const __half* Kbase = g_qkv + (size_t)b * Ss * NQKV + Dd + h * HD;
        const __half* Vbase = Kbase + Dd;

        auto issueT = [&](const __half* base, int kb, unsigned int* dst) {
            const __half* src = base + (size_t)kb * 128 * NQKV;
            #pragma unroll
            for (int q = 0; q < 4; q++) {
                int item = tid + q * 256;
                int key = item >> 3, c = item & 7;
                cpa16(s2u(dst + key * KSTRW + c * 4), src + (size_t)key * NQKV + c * 8);
            }
            CP_COMMIT();
        };

        issueT(Kbase, live[0], kb0);
        issueT(Vbase, live[0], vb0);

        // Q a-fragments (fp16, pre-scaled by 0.125*log2e)
        unsigned int qa[4][4];
        {
            int r0 = b * Ss + qi * 128 + warp * 16 + g;
            const unsigned int* q0 = (const unsigned int*)(g_qkv + (size_t)r0 * NQKV + h * HD);
            const unsigned int* q1 = (const unsigned int*)(g_qkv + (size_t)(r0 + 8) * NQKV + h * HD);
            #pragma unroll
            for (int kk = 0; kk < 4; kk++) {
                qa[kk][0] = q0[kk * 8 + t    ];
                qa[kk][1] = q1[kk * 8 + t    ];
                qa[kk][2] = q0[kk * 8 + t + 4];
                qa[kk][3] = q1[kk * 8 + t + 4];
            }
        }

        float o[8][4];
        #pragma unroll
        for (int i = 0; i < 8; i++)
            #pragma unroll
            for (int e = 0; e < 4; e++) o[i][e] = 0.f;
        float lacc[4] = {0.f, 0.f, 0.f, 0.f};

        for (int i = 0; i < nlive; i++) {
            const unsigned int* kcur = (i & 1) ? kb1 : kb0;
            unsigned int*       kalt = (i & 1) ? kb0 : kb1;
            const unsigned int* vcur = (i & 1) ? vb1 : vb0;
            unsigned int*       valt = (i & 1) ? vb0 : vb1;
            const bool nx = (i + 1 < nlive);
            const unsigned int vbytes = s2u(vcur);

            cp_wait<1>();
            __syncthreads();                     // K(i) ready; prior iter fully done

            #pragma unroll
            for (int half = 0; half < 2; half++) {
                const int kb64 = half * 64;

                float sc[8][4];
                #pragma unroll
                for (int ni = 0; ni < 8; ni++)
                    #pragma unroll
                    for (int e = 0; e < 4; e++) sc[ni][e] = -SOFT_CL2E;

                #pragma unroll
                for (int kk = 0; kk < 4; kk++) {
                    #pragma unroll
                    for (int ni = 0; ni < 8; ni++) {
                        unsigned int bb[2];
                        bb[0] = kcur[(kb64 + ni * 8 + g) * KSTRW + kk * 8 + t    ];
                        bb[1] = kcur[(kb64 + ni * 8 + g) * KSTRW + kk * 8 + t + 4];
                        mma16(sc[ni], qa[kk], bb);
                    }
                }

                if (half == 0 && nx) issueT(Kbase, live[i + 1], kalt);

                unsigned int p2[8][2];
                #pragma unroll
                for (int ni = 0; ni < 8; ni++) {
                    p2[ni][0] = ex2h2(pack2(sc[ni][0], sc[ni][1]));
                    p2[ni][1] = ex2h2(pack2(sc[ni][2], sc[ni][3]));
                }

                if (half == 0) {
                    if (nx) cp_wait<1>(); else cp_wait<0>();
                    __syncthreads();             // V(i) ready
                }

                #pragma unroll
                for (int kk = 0; kk < 4; kk++) {
                    unsigned int pa[4];
                    pa[0] = p2[2 * kk    ][0];
                    pa[1] = p2[2 * kk    ][1];
                    pa[2] = p2[2 * kk + 1][0];
                    pa[3] = p2[2 * kk + 1][1];
                    mma16(lacc, pa, bones);
                    #pragma unroll
                    for (int cp = 0; cp < 4; cp++) {
                        unsigned int r0, r1, r2, r3;
                        unsigned int addr = vbytes
                            + (unsigned int)((kb64 + kk * 16 + keyoff) * (KSTRW * 4)
                                             + (cp * 16 + coloff) * 2);
                        ldmx4t(r0, r1, r2, r3, addr);
                        unsigned int bb[2];
                        bb[0] = r0; bb[1] = r1; mma16(o[cp * 2    ], pa, bb);
                        bb[0] = r2; bb[1] = r3; mma16(o[cp * 2 + 1], pa, bb);
                    }
                }
            }

            if (nx) issueT(Vbase, live[i + 1], valt);
        }

        // ---- epilogue: normalize by l, store fp16 ----
        float inv0 = 1.0f / lacc[0], inv1 = 1.0f / lacc[2];
        int r0 = qi * 128 + warp * 16 + g;
        __half2* dst0 = (__half2*)(g_att + (size_t)(r0 + b * Ss) * Dd + h * HD);
        __half2* dst1 = (__half2*)(g_att + (size_t)(r0 + 8 + b * Ss) * Dd + h * HD);
        #pragma unroll
        for (int ni = 0; ni < 8; ni++) {
            int cw = (ni * 8 + 2 * t) >> 1;
            dst0[cw] = __floats2half2_rn(o[ni][0] * inv0, o[ni][1] * inv0);
            dst1[cw] = __floats2half2_rn(o[ni][2] * inv1, o[ni][3] * inv1);
        }
        // loop: next grab's __syncthreads orders live[]/buffer reuse
    }
}

// ---------------- launch ----------------
// 5 launches; ncu-profiled slot (index 3) = attn_kernel.
extern "C" void kernel_launch(void* const* d_in, const int* in_sizes, int n_in,
                              void* d_out, int out_size)
{
    const float*         x      = (const float*)d_in[0];
    const float*         w_qkv  = (const float*)d_in[1];
    const float*         w_proj = (const float*)d_in[2];
    const float*         b_proj = (const float*)d_in[3];
    const unsigned char* bmask  = (const unsigned char*)d_in[4];
    float*               out    = (float*)d_out;

    (void)in_sizes; (void)n_in; (void)out_size;

    cudaFuncSetAttribute(gemm_f16,    cudaFuncAttributeMaxDynamicSharedMemorySize, GEMM_SMEM);
    cudaFuncSetAttribute(attn_kernel, cudaFuncAttributeMaxDynamicSharedMemorySize, ATT_SMEM);

    void *p_x, *p_wqkvT, *p_wprojT, *p_qkv, *p_att;
    cudaGetSymbolAddress(&p_x,      g_x);
    cudaGetSymbolAddress(&p_wqkvT,  g_wqkvT);
    cudaGetSymbolAddress(&p_wprojT, g_wprojT);
    cudaGetSymbolAddress(&p_qkv,    g_qkv);
    cudaGetSymbolAddress(&p_att,    g_att);

    convert_x_mask<<<1184, 256>>>(x, bmask);                                          // 0
    transpose_fused<<<dim3(NQKV / 32 + Dd / 32, Dd / 32), dim3(32, 8)>>>(w_qkv, w_proj); // 1

    // 2: QKV [4096,1024] @ [1024,3072] -> fp16 (Q scaled 0.125*log2e)
    gemm_f16<<<dim3(NQKV / GBN, ROWS / GBM), 256, GEMM_SMEM>>>(
        (const __half*)p_x, (const __half*)p_wqkvT, nullptr, p_qkv,
        ROWS, NQKV, Dd, 1);

    attn_kernel<<<NJOBS, 256, ATT_SMEM>>>();                                          // 3 (profiled)

    // 4: proj [4096,1024] @ [1024,1024] + bias -> float out
    gemm_f16<<<dim3(Dd / GBN, ROWS / GBM), 256, GEMM_SMEM>>>(
        (const __half*)p_att, (const __half*)p_wprojT, b_proj, out,
        ROWS, Dd, Dd, 0);
}